// round 4
// baseline (speedup 1.0000x reference)
#include <cuda_runtime.h>
#include <cstdint>
#include <math.h>

#define N_TOK 8192
#define D_DIM 1024
#define H_DIM 2048
#define E_EXP 8
#define GUM_BLOCKS 32

// ---------------- scratch (no allocs allowed) ----------------
__device__ float g_logits[N_TOK * E_EXP];
__device__ int   g_expert[N_TOK];
__device__ float g_psum[GUM_BLOCKS * E_EXP];
__device__ int   g_pcnt[GUM_BLOCKS * E_EXP];
__device__ float g_pent[GUM_BLOCKS];
__device__ int   g_offsets[E_EXP + 1];
__device__ int   g_cursor[E_EXP];
__device__ int   g_list[N_TOK];
__device__ float g_h[(size_t)N_TOK * H_DIM];   // 64 MB hidden buffer

// ---------------- threefry2x32 (JAX-compatible, key = (0,42)) ----------------
__device__ __forceinline__ uint32_t rotl32(uint32_t x, uint32_t r) {
    return (x << r) | (x >> (32u - r));
}

__device__ __forceinline__ void threefry2x32_k42(uint32_t c0, uint32_t c1,
                                                 uint32_t& o0, uint32_t& o1) {
    const uint32_t k0 = 0u, k1 = 42u, k2 = 0u ^ 42u ^ 0x1BD11BDAu;
    uint32_t x0 = c0 + k0;
    uint32_t x1 = c1 + k1;
#define TFR(r) { x0 += x1; x1 = rotl32(x1, r); x1 ^= x0; }
    TFR(13u) TFR(15u) TFR(26u) TFR(6u)   x0 += k1; x1 += k2 + 1u;
    TFR(17u) TFR(29u) TFR(16u) TFR(24u)  x0 += k2; x1 += k0 + 2u;
    TFR(13u) TFR(15u) TFR(26u) TFR(6u)   x0 += k0; x1 += k1 + 3u;
    TFR(17u) TFR(29u) TFR(16u) TFR(24u)  x0 += k1; x1 += k2 + 4u;
    TFR(13u) TFR(15u) TFR(26u) TFR(6u)   x0 += k2; x1 += k0 + 5u;
#undef TFR
    o0 = x0; o1 = x1;
}

// Partitionable JAX 32-bit stream: element i -> counter (hi32(i), lo32(i)) = (0, i),
// 32-bit draw = XOR of both threefry output words.
__device__ __forceinline__ uint32_t jax_random_bits_part(uint32_t idx) {
    uint32_t o0, o1;
    threefry2x32_k42(0u, idx, o0, o1);
    return o0 ^ o1;
}

// jax.random.uniform bit manipulation: minval=1e-6, maxval=1.0
__device__ __forceinline__ float bits_to_uniform(uint32_t bits) {
    float f = __uint_as_float((bits >> 9) | 0x3f800000u) - 1.0f;
    float v = f * (1.0f - 1e-6f) + 1e-6f;
    return fmaxf(1e-6f, v);
}

// ---------------- router: relu(x@Wr1+b1)@Wr2+b2 @ ee^T -> logits ----------------
// 32 tokens per block, 256 threads, fp32 throughout (argmax stability).
__global__ __launch_bounds__(256) void router_kernel(
    const float* __restrict__ x,  const float* __restrict__ Wr1,
    const float* __restrict__ br1, const float* __restrict__ Wr2,
    const float* __restrict__ br2, const float* __restrict__ ee)
{
    __shared__ float xs[32][64];
    __shared__ float ws[64][64];
    __shared__ float t1s[32][64];
    __shared__ float embs[32][64];
    __shared__ float ees[E_EXP][64];

    int tid = threadIdx.x;
    int n0 = blockIdx.x * 32;

    for (int i = tid; i < E_EXP * 64; i += 256)
        ees[i / 64][i % 64] = ee[i];

    int nl = tid >> 3;           // local token 0..31
    int jb = (tid & 7) << 3;     // output-feature base 0..56

    float acc[8];
#pragma unroll
    for (int j = 0; j < 8; j++) acc[j] = 0.f;

    for (int k0 = 0; k0 < D_DIM; k0 += 64) {
        // x tile [32][64]
        {
            int r = tid >> 3, c = (tid & 7) << 3;
            const float* src = x + (size_t)(n0 + r) * D_DIM + k0 + c;
            *(float4*)&xs[r][c]     = *(const float4*)(src);
            *(float4*)&xs[r][c + 4] = *(const float4*)(src + 4);
        }
        // Wr1 tile [64][64]
#pragma unroll
        for (int r = 0; r < 4; r++) {
            int f  = tid + r * 256;             // float4 index 0..1023
            int kk = f >> 4, j4 = (f & 15) << 2;
            *(float4*)&ws[kk][j4] = *(const float4*)(Wr1 + (size_t)(k0 + kk) * 64 + j4);
        }
        __syncthreads();
#pragma unroll 8
        for (int k = 0; k < 64; k++) {
            float a  = xs[nl][k];
            float4 w0 = *(float4*)&ws[k][jb];
            float4 w1 = *(float4*)&ws[k][jb + 4];
            acc[0] += a * w0.x; acc[1] += a * w0.y; acc[2] += a * w0.z; acc[3] += a * w0.w;
            acc[4] += a * w1.x; acc[5] += a * w1.y; acc[6] += a * w1.z; acc[7] += a * w1.w;
        }
        __syncthreads();
    }
#pragma unroll
    for (int j = 0; j < 8; j++)
        t1s[nl][jb + j] = fmaxf(acc[j] + br1[jb + j], 0.f);

    // load Wr2 into ws
#pragma unroll
    for (int r = 0; r < 4; r++) {
        int f  = tid + r * 256;
        int kk = f >> 4, j4 = (f & 15) << 2;
        *(float4*)&ws[kk][j4] = *(const float4*)(Wr2 + (size_t)kk * 64 + j4);
    }
    __syncthreads();

    float acc2[8];
#pragma unroll
    for (int j = 0; j < 8; j++) acc2[j] = 0.f;
#pragma unroll 8
    for (int k = 0; k < 64; k++) {
        float a  = t1s[nl][k];
        float4 w0 = *(float4*)&ws[k][jb];
        float4 w1 = *(float4*)&ws[k][jb + 4];
        acc2[0] += a * w0.x; acc2[1] += a * w0.y; acc2[2] += a * w0.z; acc2[3] += a * w0.w;
        acc2[4] += a * w1.x; acc2[5] += a * w1.y; acc2[6] += a * w1.z; acc2[7] += a * w1.w;
    }
#pragma unroll
    for (int j = 0; j < 8; j++)
        embs[nl][jb + j] = acc2[j] + br2[jb + j];
    __syncthreads();

    // logits: one (token, expert) per thread
    {
        int n = tid >> 3, e = tid & 7;
        float s = 0.f;
#pragma unroll 8
        for (int k = 0; k < 64; k++) s += embs[n][k] * ees[e][k];
        g_logits[(size_t)(n0 + n) * E_EXP + e] = s;
    }
}

// ---------------- gumbel + argmax + softmax stats ----------------
__global__ __launch_bounds__(256) void gumbel_kernel() {
    int tid = threadIdx.x;
    int n = blockIdx.x * 256 + tid;

    float l[E_EXP];
#pragma unroll
    for (int e = 0; e < E_EXP; e++) l[e] = g_logits[(size_t)n * E_EXP + e];

    float mx = l[0];
#pragma unroll
    for (int e = 1; e < E_EXP; e++) mx = fmaxf(mx, l[e]);
    float p[E_EXP], s = 0.f;
#pragma unroll
    for (int e = 0; e < E_EXP; e++) { p[e] = expf(l[e] - mx); s += p[e]; }
    float inv = 1.0f / s;
    float entacc = 0.f;
#pragma unroll
    for (int e = 0; e < E_EXP; e++) {
        p[e] *= inv;
        entacc += p[e] * logf(p[e] + 1e-9f);
    }

    // gumbel argmax. Partitionable stream: bits = x0 ^ x1 of counter (0, i).
    float best = -1e30f; int bi = 0;
#pragma unroll
    for (int e = 0; e < E_EXP; e++) {
        uint32_t bits = jax_random_bits_part((uint32_t)(n * E_EXP + e));
        float u = bits_to_uniform(bits);
        float g = -logf(-logf(u));
        float z = l[e] + g;
        if (z > best) { best = z; bi = e; }
    }
    g_expert[n] = bi;

    // deterministic block reduction
    __shared__ float sp[E_EXP][256];
    __shared__ int   sc[E_EXP][256];
    __shared__ float se[256];
#pragma unroll
    for (int e = 0; e < E_EXP; e++) { sp[e][tid] = p[e]; sc[e][tid] = (bi == e) ? 1 : 0; }
    se[tid] = entacc;
    __syncthreads();
    for (int st = 128; st > 0; st >>= 1) {
        if (tid < st) {
            se[tid] += se[tid + st];
#pragma unroll
            for (int e = 0; e < E_EXP; e++) {
                sp[e][tid] += sp[e][tid + st];
                sc[e][tid] += sc[e][tid + st];
            }
        }
        __syncthreads();
    }
    if (tid == 0) {
        g_pent[blockIdx.x] = se[0];
#pragma unroll
        for (int e = 0; e < E_EXP; e++) {
            g_psum[blockIdx.x * E_EXP + e] = sp[e][0];
            g_pcnt[blockIdx.x * E_EXP + e] = sc[e][0];
        }
    }
}

// ---------------- final reduce: losses, offsets, cursor reset ----------------
__global__ void reduce_kernel(float* __restrict__ out, int out_size) {
    if (threadIdx.x != 0 || blockIdx.x != 0) return;
    float sump[E_EXP]; int cnt[E_EXP]; float ent = 0.f;
    for (int e = 0; e < E_EXP; e++) { sump[e] = 0.f; cnt[e] = 0; }
    for (int b = 0; b < GUM_BLOCKS; b++) {
        ent += g_pent[b];
        for (int e = 0; e < E_EXP; e++) {
            sump[e] += g_psum[b * E_EXP + e];
            cnt[e]  += g_pcnt[b * E_EXP + e];
        }
    }
    float lbl = 0.f;
    for (int e = 0; e < E_EXP; e++)
        lbl += ((float)cnt[e] / (float)N_TOK) * (sump[e] / (float)N_TOK);
    lbl *= (float)E_EXP;
    out[out_size - 2] = lbl;
    out[out_size - 1] = -(ent / (float)N_TOK);

    int off = 0;
    for (int e = 0; e < E_EXP; e++) {
        g_offsets[e] = off;
        off += cnt[e];
        g_cursor[e] = 0;
    }
    g_offsets[E_EXP] = off;
}

// ---------------- scatter tokens into per-expert lists ----------------
__global__ __launch_bounds__(256) void scatter_kernel() {
    int n = blockIdx.x * 256 + threadIdx.x;
    int e = g_expert[n];
    int pos = atomicAdd(&g_cursor[e], 1);
    g_list[g_offsets[e] + pos] = n;
}

// ---------------- grouped expert GEMM: 128x128x8 tiles, 8x8 reg tiles ----------------
// PHASE 1: C = relu(gather(x) @ We1[e] + be1[e]) -> g_h   (K=1024, N=2048)
// PHASE 2: C = gather(g_h) @ We2[e] + be2[e]     -> out   (K=2048, N=1024)
template <int PHASE>
__global__ __launch_bounds__(256) void expert_gemm(
    const float* __restrict__ Ain, const float* __restrict__ W,
    const float* __restrict__ bias, float* __restrict__ Cout,
    int lda, int K, int ldc)
{
    int e  = blockIdx.y >> 6;          // 64 m-tiles per expert
    int mt = blockIdx.y & 63;
    int off = g_offsets[e];
    int cnt = g_offsets[e + 1] - off;
    int m0  = mt * 128;
    if (m0 >= cnt) return;

    const float* A = (PHASE == 2) ? (const float*)g_h : Ain;
    float*       C = (PHASE == 1) ? (float*)g_h       : Cout;

    __shared__ float As[8][128];
    __shared__ float Bs[8][128];
    __shared__ int rlist[128];

    int tid = threadIdx.x;
    for (int i = tid; i < 128; i += 256) {
        int mi = m0 + i;
        rlist[i] = (mi < cnt) ? g_list[off + mi] : -1;
    }
    __syncthreads();

    int am = tid >> 1, akq = (tid & 1) * 4;
    int arow = rlist[am];
    const float* Aptr = A + (arow >= 0 ? (size_t)arow * lda : 0) + akq;
    int bk = tid >> 5, bn = (tid & 31) * 4;
    int n0 = blockIdx.x * 128;
    const float* Wb = W + (size_t)e * K * ldc + (size_t)bk * ldc + n0 + bn;

    float acc[8][8];
#pragma unroll
    for (int i = 0; i < 8; i++)
#pragma unroll
        for (int j = 0; j < 8; j++) acc[i][j] = 0.f;

    int tm = (tid >> 4) * 8, tn = (tid & 15) * 8;

    for (int k0 = 0; k0 < K; k0 += 8) {
        float4 av = (arow >= 0) ? *(const float4*)(Aptr + k0)
                                : make_float4(0.f, 0.f, 0.f, 0.f);
        float4 bv = *(const float4*)(Wb + (size_t)k0 * ldc);
        As[akq + 0][am] = av.x; As[akq + 1][am] = av.y;
        As[akq + 2][am] = av.z; As[akq + 3][am] = av.w;
        *(float4*)&Bs[bk][bn] = bv;
        __syncthreads();
#pragma unroll
        for (int kk = 0; kk < 8; kk++) {
            float a[8], b[8];
            *(float4*)&a[0] = *(float4*)&As[kk][tm];
            *(float4*)&a[4] = *(float4*)&As[kk][tm + 4];
            *(float4*)&b[0] = *(float4*)&Bs[kk][tn];
            *(float4*)&b[4] = *(float4*)&Bs[kk][tn + 4];
#pragma unroll
            for (int i = 0; i < 8; i++)
#pragma unroll
                for (int j = 0; j < 8; j++)
                    acc[i][j] += a[i] * b[j];
        }
        __syncthreads();
    }

#pragma unroll
    for (int i = 0; i < 8; i++) {
        int row = rlist[tm + i];
        if (row < 0) continue;
        float* cp = C + (size_t)row * ldc + n0 + tn;
#pragma unroll
        for (int j = 0; j < 8; j++) {
            float v = acc[i][j] + bias[(size_t)e * ldc + n0 + tn + j];
            if (PHASE == 1) v = fmaxf(v, 0.f);
            cp[j] = v;
        }
    }
}

// ---------------- launch ----------------
extern "C" void kernel_launch(void* const* d_in, const int* in_sizes, int n_in,
                              void* d_out, int out_size) {
    const float* x   = (const float*)d_in[0];
    const float* Wr1 = (const float*)d_in[1];
    const float* br1 = (const float*)d_in[2];
    const float* Wr2 = (const float*)d_in[3];
    const float* br2 = (const float*)d_in[4];
    const float* ee  = (const float*)d_in[5];
    const float* We1 = (const float*)d_in[6];
    const float* be1 = (const float*)d_in[7];
    const float* We2 = (const float*)d_in[8];
    const float* be2 = (const float*)d_in[9];
    float* out = (float*)d_out;

    router_kernel<<<N_TOK / 32, 256>>>(x, Wr1, br1, Wr2, br2, ee);
    gumbel_kernel<<<GUM_BLOCKS, 256>>>();
    reduce_kernel<<<1, 32>>>(out, out_size);
    scatter_kernel<<<N_TOK / 256, 256>>>();
    // GEMM1: [cnt_e,1024] @ [1024,2048] -> g_h
    expert_gemm<1><<<dim3(H_DIM / 128, E_EXP * 64), 256>>>(x, We1, be1, nullptr, D_DIM, D_DIM, H_DIM);
    // GEMM2: [cnt_e,2048] @ [2048,1024] -> out
    expert_gemm<2><<<dim3(D_DIM / 128, E_EXP * 64), 256>>>(nullptr, We2, be2, out, H_DIM, H_DIM, D_DIM);
}

// round 5
// speedup vs baseline: 2.2775x; 2.2775x over previous
#include <cuda_runtime.h>
#include <cstdint>
#include <math.h>

#define N_TOK 8192
#define D_DIM 1024
#define H_DIM 2048
#define E_EXP 8
#define GUM_BLOCKS 32

// ---------------- scratch (no allocs allowed) ----------------
__device__ float g_logits[N_TOK * E_EXP];
__device__ int   g_expert[N_TOK];
__device__ float g_psum[GUM_BLOCKS * E_EXP];
__device__ int   g_pcnt[GUM_BLOCKS * E_EXP];
__device__ float g_pent[GUM_BLOCKS];
__device__ int   g_offsets[E_EXP + 1];
__device__ int   g_cursor[E_EXP];
__device__ int   g_list[N_TOK];
__device__ float g_h[(size_t)N_TOK * H_DIM];   // 64 MB hidden buffer

// ---------------- threefry2x32 (JAX-compatible, key = (0,42)) ----------------
__device__ __forceinline__ uint32_t rotl32(uint32_t x, uint32_t r) {
    return (x << r) | (x >> (32u - r));
}

__device__ __forceinline__ void threefry2x32_k42(uint32_t c0, uint32_t c1,
                                                 uint32_t& o0, uint32_t& o1) {
    const uint32_t k0 = 0u, k1 = 42u, k2 = 0u ^ 42u ^ 0x1BD11BDAu;
    uint32_t x0 = c0 + k0;
    uint32_t x1 = c1 + k1;
#define TFR(r) { x0 += x1; x1 = rotl32(x1, r); x1 ^= x0; }
    TFR(13u) TFR(15u) TFR(26u) TFR(6u)   x0 += k1; x1 += k2 + 1u;
    TFR(17u) TFR(29u) TFR(16u) TFR(24u)  x0 += k2; x1 += k0 + 2u;
    TFR(13u) TFR(15u) TFR(26u) TFR(6u)   x0 += k0; x1 += k1 + 3u;
    TFR(17u) TFR(29u) TFR(16u) TFR(24u)  x0 += k1; x1 += k2 + 4u;
    TFR(13u) TFR(15u) TFR(26u) TFR(6u)   x0 += k2; x1 += k0 + 5u;
#undef TFR
    o0 = x0; o1 = x1;
}

// Partitionable JAX 32-bit stream: element i -> counter (0, i), draw = x0 ^ x1.
__device__ __forceinline__ uint32_t jax_random_bits_part(uint32_t idx) {
    uint32_t o0, o1;
    threefry2x32_k42(0u, idx, o0, o1);
    return o0 ^ o1;
}

// jax.random.uniform bit manipulation: minval=1e-6, maxval=1.0
__device__ __forceinline__ float bits_to_uniform(uint32_t bits) {
    float f = __uint_as_float((bits >> 9) | 0x3f800000u) - 1.0f;
    float v = f * (1.0f - 1e-6f) + 1e-6f;
    return fmaxf(1e-6f, v);
}

// ---------------- tf32 helpers ----------------
__device__ __forceinline__ uint32_t f2tf32(float f) {
    uint32_t u;
    asm("cvt.rna.tf32.f32 %0, %1;" : "=r"(u) : "f"(f));
    return u;
}

__device__ __forceinline__ void mma_tf32(float* d, const uint32_t* a, const uint32_t* b) {
    asm volatile(
        "mma.sync.aligned.m16n8k8.row.col.f32.tf32.tf32.f32 "
        "{%0,%1,%2,%3}, {%4,%5,%6,%7}, {%8,%9}, {%0,%1,%2,%3};\n"
        : "+f"(d[0]), "+f"(d[1]), "+f"(d[2]), "+f"(d[3])
        : "r"(a[0]), "r"(a[1]), "r"(a[2]), "r"(a[3]), "r"(b[0]), "r"(b[1]));
}

// ---------------- router: relu(x@Wr1+b1)@Wr2+b2 @ ee^T -> logits ----------------
__global__ __launch_bounds__(256) void router_kernel(
    const float* __restrict__ x,  const float* __restrict__ Wr1,
    const float* __restrict__ br1, const float* __restrict__ Wr2,
    const float* __restrict__ br2, const float* __restrict__ ee)
{
    __shared__ float xs[32][64];
    __shared__ float ws[64][64];
    __shared__ float t1s[32][64];
    __shared__ float embs[32][64];
    __shared__ float ees[E_EXP][64];

    int tid = threadIdx.x;
    int n0 = blockIdx.x * 32;

    for (int i = tid; i < E_EXP * 64; i += 256)
        ees[i / 64][i % 64] = ee[i];

    int nl = tid >> 3;
    int jb = (tid & 7) << 3;

    float acc[8];
#pragma unroll
    for (int j = 0; j < 8; j++) acc[j] = 0.f;

    for (int k0 = 0; k0 < D_DIM; k0 += 64) {
        {
            int r = tid >> 3, c = (tid & 7) << 3;
            const float* src = x + (size_t)(n0 + r) * D_DIM + k0 + c;
            *(float4*)&xs[r][c]     = *(const float4*)(src);
            *(float4*)&xs[r][c + 4] = *(const float4*)(src + 4);
        }
#pragma unroll
        for (int r = 0; r < 4; r++) {
            int f  = tid + r * 256;
            int kk = f >> 4, j4 = (f & 15) << 2;
            *(float4*)&ws[kk][j4] = *(const float4*)(Wr1 + (size_t)(k0 + kk) * 64 + j4);
        }
        __syncthreads();
#pragma unroll 8
        for (int k = 0; k < 64; k++) {
            float a  = xs[nl][k];
            float4 w0 = *(float4*)&ws[k][jb];
            float4 w1 = *(float4*)&ws[k][jb + 4];
            acc[0] += a * w0.x; acc[1] += a * w0.y; acc[2] += a * w0.z; acc[3] += a * w0.w;
            acc[4] += a * w1.x; acc[5] += a * w1.y; acc[6] += a * w1.z; acc[7] += a * w1.w;
        }
        __syncthreads();
    }
#pragma unroll
    for (int j = 0; j < 8; j++)
        t1s[nl][jb + j] = fmaxf(acc[j] + br1[jb + j], 0.f);

#pragma unroll
    for (int r = 0; r < 4; r++) {
        int f  = tid + r * 256;
        int kk = f >> 4, j4 = (f & 15) << 2;
        *(float4*)&ws[kk][j4] = *(const float4*)(Wr2 + (size_t)kk * 64 + j4);
    }
    __syncthreads();

    float acc2[8];
#pragma unroll
    for (int j = 0; j < 8; j++) acc2[j] = 0.f;
#pragma unroll 8
    for (int k = 0; k < 64; k++) {
        float a  = t1s[nl][k];
        float4 w0 = *(float4*)&ws[k][jb];
        float4 w1 = *(float4*)&ws[k][jb + 4];
        acc2[0] += a * w0.x; acc2[1] += a * w0.y; acc2[2] += a * w0.z; acc2[3] += a * w0.w;
        acc2[4] += a * w1.x; acc2[5] += a * w1.y; acc2[6] += a * w1.z; acc2[7] += a * w1.w;
    }
#pragma unroll
    for (int j = 0; j < 8; j++)
        embs[nl][jb + j] = acc2[j] + br2[jb + j];
    __syncthreads();

    {
        int n = tid >> 3, e = tid & 7;
        float s = 0.f;
#pragma unroll 8
        for (int k = 0; k < 64; k++) s += embs[n][k] * ees[e][k];
        g_logits[(size_t)(n0 + n) * E_EXP + e] = s;
    }
}

// ---------------- gumbel + argmax + softmax stats ----------------
__global__ __launch_bounds__(256) void gumbel_kernel() {
    int tid = threadIdx.x;
    int n = blockIdx.x * 256 + tid;

    float l[E_EXP];
#pragma unroll
    for (int e = 0; e < E_EXP; e++) l[e] = g_logits[(size_t)n * E_EXP + e];

    float mx = l[0];
#pragma unroll
    for (int e = 1; e < E_EXP; e++) mx = fmaxf(mx, l[e]);
    float p[E_EXP], s = 0.f;
#pragma unroll
    for (int e = 0; e < E_EXP; e++) { p[e] = expf(l[e] - mx); s += p[e]; }
    float inv = 1.0f / s;
    float entacc = 0.f;
#pragma unroll
    for (int e = 0; e < E_EXP; e++) {
        p[e] *= inv;
        entacc += p[e] * logf(p[e] + 1e-9f);
    }

    float best = -1e30f; int bi = 0;
#pragma unroll
    for (int e = 0; e < E_EXP; e++) {
        uint32_t bits = jax_random_bits_part((uint32_t)(n * E_EXP + e));
        float u = bits_to_uniform(bits);
        float g = -logf(-logf(u));
        float z = l[e] + g;
        if (z > best) { best = z; bi = e; }
    }
    g_expert[n] = bi;

    __shared__ float sp[E_EXP][256];
    __shared__ int   sc[E_EXP][256];
    __shared__ float se[256];
#pragma unroll
    for (int e = 0; e < E_EXP; e++) { sp[e][tid] = p[e]; sc[e][tid] = (bi == e) ? 1 : 0; }
    se[tid] = entacc;
    __syncthreads();
    for (int st = 128; st > 0; st >>= 1) {
        if (tid < st) {
            se[tid] += se[tid + st];
#pragma unroll
            for (int e = 0; e < E_EXP; e++) {
                sp[e][tid] += sp[e][tid + st];
                sc[e][tid] += sc[e][tid + st];
            }
        }
        __syncthreads();
    }
    if (tid == 0) {
        g_pent[blockIdx.x] = se[0];
#pragma unroll
        for (int e = 0; e < E_EXP; e++) {
            g_psum[blockIdx.x * E_EXP + e] = sp[e][0];
            g_pcnt[blockIdx.x * E_EXP + e] = sc[e][0];
        }
    }
}

// ---------------- final reduce: losses, offsets, cursor reset ----------------
__global__ void reduce_kernel(float* __restrict__ out, int out_size) {
    if (threadIdx.x != 0 || blockIdx.x != 0) return;
    float sump[E_EXP]; int cnt[E_EXP]; float ent = 0.f;
    for (int e = 0; e < E_EXP; e++) { sump[e] = 0.f; cnt[e] = 0; }
    for (int b = 0; b < GUM_BLOCKS; b++) {
        ent += g_pent[b];
        for (int e = 0; e < E_EXP; e++) {
            sump[e] += g_psum[b * E_EXP + e];
            cnt[e]  += g_pcnt[b * E_EXP + e];
        }
    }
    float lbl = 0.f;
    for (int e = 0; e < E_EXP; e++)
        lbl += ((float)cnt[e] / (float)N_TOK) * (sump[e] / (float)N_TOK);
    lbl *= (float)E_EXP;
    out[out_size - 2] = lbl;
    out[out_size - 1] = -(ent / (float)N_TOK);

    int off = 0;
    for (int e = 0; e < E_EXP; e++) {
        g_offsets[e] = off;
        off += cnt[e];
        g_cursor[e] = 0;
    }
    g_offsets[E_EXP] = off;
}

// ---------------- scatter tokens into per-expert lists ----------------
__global__ __launch_bounds__(256) void scatter_kernel() {
    int n = blockIdx.x * 256 + threadIdx.x;
    int e = g_expert[n];
    int pos = atomicAdd(&g_cursor[e], 1);
    g_list[g_offsets[e] + pos] = n;
}

// ---------------- grouped expert GEMM on tensor cores (TF32 mma.sync) ----------------
// 128x128 block tile, K-step 16, double-buffered SMEM, 8 warps (2x4), each warp
// computes 64x32 via 4x4 m16n8k8 fragments. A rows gathered via rlist; values
// converted fp32 -> tf32 at staging.
// PHASE 1: C = relu(gather(x) @ We1[e] + be1[e]) -> g_h   (K=1024, N=2048)
// PHASE 2: C = gather(g_h) @ We2[e] + be2[e]     -> out   (K=2048, N=1024)
#define AS_STRIDE 20    // 16 k + 4 pad (floats) -> conflict-free A frag LDS
#define BS_STRIDE 136   // 128 n + 8 pad (floats) -> conflict-free B frag LDS

template <int PHASE>
__global__ __launch_bounds__(256) void expert_gemm_mma(
    const float* __restrict__ Ain, const float* __restrict__ W,
    const float* __restrict__ bias, float* __restrict__ Cout,
    int lda, int K, int ldc)
{
    int e  = blockIdx.y >> 6;          // 64 m-tiles per expert
    int mt = blockIdx.y & 63;
    int off = g_offsets[e];
    int cnt = g_offsets[e + 1] - off;
    int m0  = mt * 128;
    if (m0 >= cnt) return;

    const float* A = (PHASE == 2) ? (const float*)g_h : Ain;
    float*       C = (PHASE == 1) ? (float*)g_h       : Cout;

    __shared__ uint32_t As[2][128 * AS_STRIDE];
    __shared__ uint32_t Bs[2][16 * BS_STRIDE];
    __shared__ int rlist[128];

    int tid  = threadIdx.x;
    int wid  = tid >> 5;
    int lane = tid & 31;
    int gid  = lane >> 2;     // 0..7
    int tig  = lane & 3;      // 0..3
    int warp_m = wid >> 2;    // 0..1
    int warp_n = wid & 3;     // 0..3
    int wm_base = warp_m * 64;
    int wn_base = warp_n * 32;
    int n0 = blockIdx.x * 128;

    for (int i = tid; i < 128; i += 256) {
        int mi = m0 + i;
        rlist[i] = (mi < cnt) ? g_list[off + mi] : -1;
    }
    __syncthreads();

    // staging roles
    int a_row = tid >> 1;            // 0..127
    int a_k   = (tid & 1) * 8;       // 0 or 8
    int arow_g = rlist[a_row];
    const float* Abase = A + (size_t)(arow_g >= 0 ? arow_g : 0) * lda + a_k;
    int b_k = tid >> 4;              // 0..15
    int b_n = (tid & 15) * 8;        // 0..120
    const float* Bbase = W + (size_t)e * K * ldc + (size_t)b_k * ldc + n0 + b_n;

    float acc[4][4][4];
#pragma unroll
    for (int i = 0; i < 4; i++)
#pragma unroll
        for (int j = 0; j < 4; j++)
#pragma unroll
            for (int r = 0; r < 4; r++) acc[i][j][r] = 0.f;

    float4 av0, av1, bv0, bv1;
    const float4 z4 = make_float4(0.f, 0.f, 0.f, 0.f);

    // prologue: load + stage k0 = 0 into buf 0
    if (arow_g >= 0) {
        av0 = *(const float4*)(Abase);
        av1 = *(const float4*)(Abase + 4);
    } else { av0 = z4; av1 = z4; }
    bv0 = *(const float4*)(Bbase);
    bv1 = *(const float4*)(Bbase + 4);
    {
        uint4 u;
        u.x = f2tf32(av0.x); u.y = f2tf32(av0.y); u.z = f2tf32(av0.z); u.w = f2tf32(av0.w);
        *(uint4*)&As[0][a_row * AS_STRIDE + a_k] = u;
        u.x = f2tf32(av1.x); u.y = f2tf32(av1.y); u.z = f2tf32(av1.z); u.w = f2tf32(av1.w);
        *(uint4*)&As[0][a_row * AS_STRIDE + a_k + 4] = u;
        u.x = f2tf32(bv0.x); u.y = f2tf32(bv0.y); u.z = f2tf32(bv0.z); u.w = f2tf32(bv0.w);
        *(uint4*)&Bs[0][b_k * BS_STRIDE + b_n] = u;
        u.x = f2tf32(bv1.x); u.y = f2tf32(bv1.y); u.z = f2tf32(bv1.z); u.w = f2tf32(bv1.w);
        *(uint4*)&Bs[0][b_k * BS_STRIDE + b_n + 4] = u;
    }
    __syncthreads();

    int buf = 0;
    for (int k0 = 16; ; k0 += 16) {
        bool has = (k0 < K);
        if (has) {
            if (arow_g >= 0) {
                av0 = *(const float4*)(Abase + k0);
                av1 = *(const float4*)(Abase + k0 + 4);
            } else { av0 = z4; av1 = z4; }
            bv0 = *(const float4*)(Bbase + (size_t)k0 * ldc);
            bv1 = *(const float4*)(Bbase + (size_t)k0 * ldc + 4);
        }

        // compute current buffer
        {
            const uint32_t* as = As[buf];
            const uint32_t* bs = Bs[buf];
#pragma unroll
            for (int k8 = 0; k8 < 2; k8++) {
                int c = k8 * 8 + tig;
                uint32_t af[4][4];
#pragma unroll
                for (int wm = 0; wm < 4; wm++) {
                    int m = wm_base + wm * 16 + gid;
                    af[wm][0] = as[m * AS_STRIDE + c];
                    af[wm][1] = as[(m + 8) * AS_STRIDE + c];
                    af[wm][2] = as[m * AS_STRIDE + c + 4];
                    af[wm][3] = as[(m + 8) * AS_STRIDE + c + 4];
                }
                uint32_t bf[4][2];
#pragma unroll
                for (int wn = 0; wn < 4; wn++) {
                    int n = wn_base + wn * 8 + gid;
                    bf[wn][0] = bs[c * BS_STRIDE + n];
                    bf[wn][1] = bs[(c + 4) * BS_STRIDE + n];
                }
#pragma unroll
                for (int wm = 0; wm < 4; wm++)
#pragma unroll
                    for (int wn = 0; wn < 4; wn++)
                        mma_tf32(acc[wm][wn], af[wm], bf[wn]);
            }
        }

        if (!has) break;
        __syncthreads();
        {
            int nb = buf ^ 1;
            uint4 u;
            u.x = f2tf32(av0.x); u.y = f2tf32(av0.y); u.z = f2tf32(av0.z); u.w = f2tf32(av0.w);
            *(uint4*)&As[nb][a_row * AS_STRIDE + a_k] = u;
            u.x = f2tf32(av1.x); u.y = f2tf32(av1.y); u.z = f2tf32(av1.z); u.w = f2tf32(av1.w);
            *(uint4*)&As[nb][a_row * AS_STRIDE + a_k + 4] = u;
            u.x = f2tf32(bv0.x); u.y = f2tf32(bv0.y); u.z = f2tf32(bv0.z); u.w = f2tf32(bv0.w);
            *(uint4*)&Bs[nb][b_k * BS_STRIDE + b_n] = u;
            u.x = f2tf32(bv1.x); u.y = f2tf32(bv1.y); u.z = f2tf32(bv1.z); u.w = f2tf32(bv1.w);
            *(uint4*)&Bs[nb][b_k * BS_STRIDE + b_n + 4] = u;
        }
        __syncthreads();
        buf ^= 1;
    }

    // epilogue: bias (+relu) and scatter-store
#pragma unroll
    for (int wm = 0; wm < 4; wm++) {
        int ml = wm_base + wm * 16 + gid;
        int r0 = rlist[ml];
        int r1 = rlist[ml + 8];
#pragma unroll
        for (int wn = 0; wn < 4; wn++) {
            int col = n0 + wn_base + wn * 8 + tig * 2;
            float2 bv = *(const float2*)&bias[(size_t)e * ldc + col];
            const float* a = acc[wm][wn];
            if (r0 >= 0) {
                float2 v = make_float2(a[0] + bv.x, a[1] + bv.y);
                if (PHASE == 1) { v.x = fmaxf(v.x, 0.f); v.y = fmaxf(v.y, 0.f); }
                *(float2*)&C[(size_t)r0 * ldc + col] = v;
            }
            if (r1 >= 0) {
                float2 v = make_float2(a[2] + bv.x, a[3] + bv.y);
                if (PHASE == 1) { v.x = fmaxf(v.x, 0.f); v.y = fmaxf(v.y, 0.f); }
                *(float2*)&C[(size_t)r1 * ldc + col] = v;
            }
        }
    }
}

// ---------------- launch ----------------
extern "C" void kernel_launch(void* const* d_in, const int* in_sizes, int n_in,
                              void* d_out, int out_size) {
    const float* x   = (const float*)d_in[0];
    const float* Wr1 = (const float*)d_in[1];
    const float* br1 = (const float*)d_in[2];
    const float* Wr2 = (const float*)d_in[3];
    const float* br2 = (const float*)d_in[4];
    const float* ee  = (const float*)d_in[5];
    const float* We1 = (const float*)d_in[6];
    const float* be1 = (const float*)d_in[7];
    const float* We2 = (const float*)d_in[8];
    const float* be2 = (const float*)d_in[9];
    float* out = (float*)d_out;

    router_kernel<<<N_TOK / 32, 256>>>(x, Wr1, br1, Wr2, br2, ee);
    gumbel_kernel<<<GUM_BLOCKS, 256>>>();
    reduce_kernel<<<1, 32>>>(out, out_size);
    scatter_kernel<<<N_TOK / 256, 256>>>();
    expert_gemm_mma<1><<<dim3(H_DIM / 128, E_EXP * 64), 256>>>(x, We1, be1, nullptr, D_DIM, D_DIM, H_DIM);
    expert_gemm_mma<2><<<dim3(D_DIM / 128, E_EXP * 64), 256>>>(nullptr, We2, be2, out, H_DIM, H_DIM, D_DIM);
}

// round 8
// speedup vs baseline: 3.0653x; 1.3459x over previous
#include <cuda_runtime.h>
#include <cuda_fp16.h>
#include <cstdint>
#include <math.h>

#define N_TOK 8192
#define D_DIM 1024
#define H_DIM 2048
#define E_EXP 8
#define GUM_BLOCKS 32

// ---------------- scratch (no allocs allowed) ----------------
__device__ float g_logits[N_TOK * E_EXP];
__device__ int   g_expert[N_TOK];
__device__ float g_psum[GUM_BLOCKS * E_EXP];
__device__ int   g_pcnt[GUM_BLOCKS * E_EXP];
__device__ float g_pent[GUM_BLOCKS];
__device__ int   g_offsets[E_EXP + 1];
__device__ int   g_cursor[E_EXP];
__device__ int   g_list[N_TOK];
__device__ float g_h[(size_t)N_TOK * H_DIM];   // 64 MB hidden buffer

// ---------------- threefry2x32 (JAX-compatible, key = (0,42)) ----------------
__device__ __forceinline__ uint32_t rotl32(uint32_t x, uint32_t r) {
    return (x << r) | (x >> (32u - r));
}

__device__ __forceinline__ void threefry2x32_k42(uint32_t c0, uint32_t c1,
                                                 uint32_t& o0, uint32_t& o1) {
    const uint32_t k0 = 0u, k1 = 42u, k2 = 0u ^ 42u ^ 0x1BD11BDAu;
    uint32_t x0 = c0 + k0;
    uint32_t x1 = c1 + k1;
#define TFR(r) { x0 += x1; x1 = rotl32(x1, r); x1 ^= x0; }
    TFR(13u) TFR(15u) TFR(26u) TFR(6u)   x0 += k1; x1 += k2 + 1u;
    TFR(17u) TFR(29u) TFR(16u) TFR(24u)  x0 += k2; x1 += k0 + 2u;
    TFR(13u) TFR(15u) TFR(26u) TFR(6u)   x0 += k0; x1 += k1 + 3u;
    TFR(17u) TFR(29u) TFR(16u) TFR(24u)  x0 += k1; x1 += k2 + 4u;
    TFR(13u) TFR(15u) TFR(26u) TFR(6u)   x0 += k2; x1 += k0 + 5u;
#undef TFR
    o0 = x0; o1 = x1;
}

// Partitionable JAX 32-bit stream: element i -> counter (0, i), draw = x0 ^ x1.
__device__ __forceinline__ uint32_t jax_random_bits_part(uint32_t idx) {
    uint32_t o0, o1;
    threefry2x32_k42(0u, idx, o0, o1);
    return o0 ^ o1;
}

// jax.random.uniform bit manipulation: minval=1e-6, maxval=1.0
__device__ __forceinline__ float bits_to_uniform(uint32_t bits) {
    float f = __uint_as_float((bits >> 9) | 0x3f800000u) - 1.0f;
    float v = f * (1.0f - 1e-6f) + 1e-6f;
    return fmaxf(1e-6f, v);
}

// ---------------- fp16 helpers ----------------
// pack two f32 -> f16x2 (lo = a, hi = b), round-to-nearest
__device__ __forceinline__ uint32_t f2h2(float a, float b) {
    uint32_t u;
    asm("cvt.rn.f16x2.f32 %0, %1, %2;" : "=r"(u) : "f"(b), "f"(a));
    return u;
}

__device__ __forceinline__ void mma_f16(float* d, const uint32_t* a, const uint32_t* b) {
    asm volatile(
        "mma.sync.aligned.m16n8k16.row.col.f32.f16.f16.f32 "
        "{%0,%1,%2,%3}, {%4,%5,%6,%7}, {%8,%9}, {%0,%1,%2,%3};\n"
        : "+f"(d[0]), "+f"(d[1]), "+f"(d[2]), "+f"(d[3])
        : "r"(a[0]), "r"(a[1]), "r"(a[2]), "r"(a[3]), "r"(b[0]), "r"(b[1]));
}

// ---------------- router: relu(x@Wr1+b1)@Wr2+b2 @ ee^T -> logits ----------------
__global__ __launch_bounds__(256) void router_kernel(
    const float* __restrict__ x,  const float* __restrict__ Wr1,
    const float* __restrict__ br1, const float* __restrict__ Wr2,
    const float* __restrict__ br2, const float* __restrict__ ee)
{
    __shared__ float xs[32][64];
    __shared__ float ws[64][64];
    __shared__ float t1s[32][64];
    __shared__ float embs[32][64];
    __shared__ float ees[E_EXP][64];

    int tid = threadIdx.x;
    int n0 = blockIdx.x * 32;

    for (int i = tid; i < E_EXP * 64; i += 256)
        ees[i / 64][i % 64] = ee[i];

    int nl = tid >> 3;
    int jb = (tid & 7) << 3;

    float acc[8];
#pragma unroll
    for (int j = 0; j < 8; j++) acc[j] = 0.f;

    for (int k0 = 0; k0 < D_DIM; k0 += 64) {
        {
            int r = tid >> 3, c = (tid & 7) << 3;
            const float* src = x + (size_t)(n0 + r) * D_DIM + k0 + c;
            *(float4*)&xs[r][c]     = *(const float4*)(src);
            *(float4*)&xs[r][c + 4] = *(const float4*)(src + 4);
        }
#pragma unroll
        for (int r = 0; r < 4; r++) {
            int f  = tid + r * 256;
            int kk = f >> 4, j4 = (f & 15) << 2;
            *(float4*)&ws[kk][j4] = *(const float4*)(Wr1 + (size_t)(k0 + kk) * 64 + j4);
        }
        __syncthreads();
#pragma unroll 8
        for (int k = 0; k < 64; k++) {
            float a  = xs[nl][k];
            float4 w0 = *(float4*)&ws[k][jb];
            float4 w1 = *(float4*)&ws[k][jb + 4];
            acc[0] += a * w0.x; acc[1] += a * w0.y; acc[2] += a * w0.z; acc[3] += a * w0.w;
            acc[4] += a * w1.x; acc[5] += a * w1.y; acc[6] += a * w1.z; acc[7] += a * w1.w;
        }
        __syncthreads();
    }
#pragma unroll
    for (int j = 0; j < 8; j++)
        t1s[nl][jb + j] = fmaxf(acc[j] + br1[jb + j], 0.f);

#pragma unroll
    for (int r = 0; r < 4; r++) {
        int f  = tid + r * 256;
        int kk = f >> 4, j4 = (f & 15) << 2;
        *(float4*)&ws[kk][j4] = *(const float4*)(Wr2 + (size_t)kk * 64 + j4);
    }
    __syncthreads();

    float acc2[8];
#pragma unroll
    for (int j = 0; j < 8; j++) acc2[j] = 0.f;
#pragma unroll 8
    for (int k = 0; k < 64; k++) {
        float a  = t1s[nl][k];
        float4 w0 = *(float4*)&ws[k][jb];
        float4 w1 = *(float4*)&ws[k][jb + 4];
        acc2[0] += a * w0.x; acc2[1] += a * w0.y; acc2[2] += a * w0.z; acc2[3] += a * w0.w;
        acc2[4] += a * w1.x; acc2[5] += a * w1.y; acc2[6] += a * w1.z; acc2[7] += a * w1.w;
    }
#pragma unroll
    for (int j = 0; j < 8; j++)
        embs[nl][jb + j] = acc2[j] + br2[jb + j];
    __syncthreads();

    {
        int n = tid >> 3, e = tid & 7;
        float s = 0.f;
#pragma unroll 8
        for (int k = 0; k < 64; k++) s += embs[n][k] * ees[e][k];
        g_logits[(size_t)(n0 + n) * E_EXP + e] = s;
    }
}

// ---------------- gumbel + argmax + softmax stats ----------------
__global__ __launch_bounds__(256) void gumbel_kernel() {
    int tid = threadIdx.x;
    int n = blockIdx.x * 256 + tid;

    float l[E_EXP];
#pragma unroll
    for (int e = 0; e < E_EXP; e++) l[e] = g_logits[(size_t)n * E_EXP + e];

    float mx = l[0];
#pragma unroll
    for (int e = 1; e < E_EXP; e++) mx = fmaxf(mx, l[e]);
    float p[E_EXP], s = 0.f;
#pragma unroll
    for (int e = 0; e < E_EXP; e++) { p[e] = expf(l[e] - mx); s += p[e]; }
    float inv = 1.0f / s;
    float entacc = 0.f;
#pragma unroll
    for (int e = 0; e < E_EXP; e++) {
        p[e] *= inv;
        entacc += p[e] * logf(p[e] + 1e-9f);
    }

    float best = -1e30f; int bi = 0;
#pragma unroll
    for (int e = 0; e < E_EXP; e++) {
        uint32_t bits = jax_random_bits_part((uint32_t)(n * E_EXP + e));
        float u = bits_to_uniform(bits);
        float g = -logf(-logf(u));
        float z = l[e] + g;
        if (z > best) { best = z; bi = e; }
    }
    g_expert[n] = bi;

    __shared__ float sp[E_EXP][256];
    __shared__ int   sc[E_EXP][256];
    __shared__ float se[256];
#pragma unroll
    for (int e = 0; e < E_EXP; e++) { sp[e][tid] = p[e]; sc[e][tid] = (bi == e) ? 1 : 0; }
    se[tid] = entacc;
    __syncthreads();
    for (int st = 128; st > 0; st >>= 1) {
        if (tid < st) {
            se[tid] += se[tid + st];
#pragma unroll
            for (int e = 0; e < E_EXP; e++) {
                sp[e][tid] += sp[e][tid + st];
                sc[e][tid] += sc[e][tid + st];
            }
        }
        __syncthreads();
    }
    if (tid == 0) {
        g_pent[blockIdx.x] = se[0];
#pragma unroll
        for (int e = 0; e < E_EXP; e++) {
            g_psum[blockIdx.x * E_EXP + e] = sp[e][0];
            g_pcnt[blockIdx.x * E_EXP + e] = sc[e][0];
        }
    }
}

// ---------------- final reduce: losses, offsets, cursor reset ----------------
__global__ void reduce_kernel(float* __restrict__ out, int out_size) {
    if (threadIdx.x != 0 || blockIdx.x != 0) return;
    float sump[E_EXP]; int cnt[E_EXP]; float ent = 0.f;
    for (int e = 0; e < E_EXP; e++) { sump[e] = 0.f; cnt[e] = 0; }
    for (int b = 0; b < GUM_BLOCKS; b++) {
        ent += g_pent[b];
        for (int e = 0; e < E_EXP; e++) {
            sump[e] += g_psum[b * E_EXP + e];
            cnt[e]  += g_pcnt[b * E_EXP + e];
        }
    }
    float lbl = 0.f;
    for (int e = 0; e < E_EXP; e++)
        lbl += ((float)cnt[e] / (float)N_TOK) * (sump[e] / (float)N_TOK);
    lbl *= (float)E_EXP;
    out[out_size - 2] = lbl;
    out[out_size - 1] = -(ent / (float)N_TOK);

    int off = 0;
    for (int e = 0; e < E_EXP; e++) {
        g_offsets[e] = off;
        off += cnt[e];
        g_cursor[e] = 0;
    }
    g_offsets[E_EXP] = off;
}

// ---------------- scatter tokens into per-expert lists ----------------
__global__ __launch_bounds__(256) void scatter_kernel() {
    int n = blockIdx.x * 256 + threadIdx.x;
    int e = g_expert[n];
    int pos = atomicAdd(&g_cursor[e], 1);
    g_list[g_offsets[e] + pos] = n;
}

// ---------------- grouped expert GEMM on tensor cores (FP16 m16n8k16) ----------
// 128x128 block tile, K-step 16, double-buffered SMEM, 8 warps (2x4), each warp
// computes 64x32 via 4x4 m16n8k16 fragments. A rows gathered via rlist; inputs
// converted fp32 -> fp16 (RN) at staging; fp32 accumulate in the mma.
// A tile: [row][kpair] u32, stride 12 (8 data + 4 pad) -> conflict-free frag LDS
// B tile: [k][n] halves, stride 68 u32 (64 data + 4 pad) -> conflict-free u16 LDS
#define AS_STRIDE 12
#define BS_STRIDE 68

template <int PHASE>
__global__ __launch_bounds__(256) void expert_gemm_mma(
    const float* __restrict__ Ain, const float* __restrict__ W,
    const float* __restrict__ bias, float* __restrict__ Cout,
    int lda, int K, int ldc)
{
    int e  = blockIdx.y >> 6;          // 64 m-tiles per expert
    int mt = blockIdx.y & 63;
    int off = g_offsets[e];
    int cnt = g_offsets[e + 1] - off;
    int m0  = mt * 128;
    if (m0 >= cnt) return;

    const float* A = (PHASE == 2) ? (const float*)g_h : Ain;
    float*       C = (PHASE == 1) ? (float*)g_h       : Cout;

    __shared__ uint32_t As[2][128 * AS_STRIDE];
    __shared__ uint32_t Bs[2][16 * BS_STRIDE];
    __shared__ int rlist[128];

    int tid  = threadIdx.x;
    int wid  = tid >> 5;
    int lane = tid & 31;
    int gid  = lane >> 2;     // 0..7
    int tig  = lane & 3;      // 0..3
    int warp_m = wid >> 2;    // 0..1
    int warp_n = wid & 3;     // 0..3
    int wm_base = warp_m * 64;
    int wn_base = warp_n * 32;
    int n0 = blockIdx.x * 128;

    for (int i = tid; i < 128; i += 256) {
        int mi = m0 + i;
        rlist[i] = (mi < cnt) ? g_list[off + mi] : -1;
    }
    __syncthreads();

    // staging roles
    int a_row = tid >> 1;            // 0..127
    int a_k   = (tid & 1) * 8;       // 0 or 8 (float offset)
    int arow_g = rlist[a_row];
    const float* Abase = A + (size_t)(arow_g >= 0 ? arow_g : 0) * lda + a_k;
    int b_k = tid >> 4;              // 0..15
    int b_n = (tid & 15) * 8;        // 0..120
    const float* Bbase = W + (size_t)e * K * ldc + (size_t)b_k * ldc + n0 + b_n;

    float acc[4][4][4];
#pragma unroll
    for (int i = 0; i < 4; i++)
#pragma unroll
        for (int j = 0; j < 4; j++)
#pragma unroll
            for (int r = 0; r < 4; r++) acc[i][j][r] = 0.f;

    float4 av0, av1, bv0, bv1;
    const float4 z4 = make_float4(0.f, 0.f, 0.f, 0.f);

    // prologue: load + stage k0 = 0 into buf 0
    if (arow_g >= 0) {
        av0 = *(const float4*)(Abase);
        av1 = *(const float4*)(Abase + 4);
    } else { av0 = z4; av1 = z4; }
    bv0 = *(const float4*)(Bbase);
    bv1 = *(const float4*)(Bbase + 4);
    {
        uint4 u;
        u.x = f2h2(av0.x, av0.y); u.y = f2h2(av0.z, av0.w);
        u.z = f2h2(av1.x, av1.y); u.w = f2h2(av1.z, av1.w);
        *(uint4*)&As[0][a_row * AS_STRIDE + (a_k >> 1)] = u;
        u.x = f2h2(bv0.x, bv0.y); u.y = f2h2(bv0.z, bv0.w);
        u.z = f2h2(bv1.x, bv1.y); u.w = f2h2(bv1.z, bv1.w);
        *(uint4*)&Bs[0][b_k * BS_STRIDE + (b_n >> 1)] = u;
    }
    __syncthreads();

    int buf = 0;
    for (int k0 = 16; ; k0 += 16) {
        bool has = (k0 < K);
        if (has) {
            if (arow_g >= 0) {
                av0 = *(const float4*)(Abase + k0);
                av1 = *(const float4*)(Abase + k0 + 4);
            } else { av0 = z4; av1 = z4; }
            bv0 = *(const float4*)(Bbase + (size_t)k0 * ldc);
            bv1 = *(const float4*)(Bbase + (size_t)k0 * ldc + 4);
        }

        // compute current buffer: one m16n8k16 step per fragment pair
        {
            const uint32_t* as = As[buf];
            const unsigned short* bsh = (const unsigned short*)Bs[buf];

            uint32_t af[4][4];
#pragma unroll
            for (int wm = 0; wm < 4; wm++) {
                int m = wm_base + wm * 16 + gid;
                af[wm][0] = as[m * AS_STRIDE + tig];
                af[wm][1] = as[(m + 8) * AS_STRIDE + tig];
                af[wm][2] = as[m * AS_STRIDE + tig + 4];
                af[wm][3] = as[(m + 8) * AS_STRIDE + tig + 4];
            }
            uint32_t bf[4][2];
#pragma unroll
            for (int wn = 0; wn < 4; wn++) {
                int col = wn_base + wn * 8 + gid;
                int k0b = tig * 2;
                uint32_t lo0 = bsh[(k0b)     * (BS_STRIDE * 2) + col];
                uint32_t hi0 = bsh[(k0b + 1) * (BS_STRIDE * 2) + col];
                uint32_t lo1 = bsh[(k0b + 8) * (BS_STRIDE * 2) + col];
                uint32_t hi1 = bsh[(k0b + 9) * (BS_STRIDE * 2) + col];
                bf[wn][0] = lo0 | (hi0 << 16);
                bf[wn][1] = lo1 | (hi1 << 16);
            }
#pragma unroll
            for (int wm = 0; wm < 4; wm++)
#pragma unroll
                for (int wn = 0; wn < 4; wn++)
                    mma_f16(acc[wm][wn], af[wm], bf[wn]);
        }

        if (!has) break;
        __syncthreads();
        {
            int nb = buf ^ 1;
            uint4 u;
            u.x = f2h2(av0.x, av0.y); u.y = f2h2(av0.z, av0.w);
            u.z = f2h2(av1.x, av1.y); u.w = f2h2(av1.z, av1.w);
            *(uint4*)&As[nb][a_row * AS_STRIDE + (a_k >> 1)] = u;
            u.x = f2h2(bv0.x, bv0.y); u.y = f2h2(bv0.z, bv0.w);
            u.z = f2h2(bv1.x, bv1.y); u.w = f2h2(bv1.z, bv1.w);
            *(uint4*)&Bs[nb][b_k * BS_STRIDE + (b_n >> 1)] = u;
        }
        __syncthreads();
        buf ^= 1;
    }

    // epilogue: bias (+relu) and scatter-store
#pragma unroll
    for (int wm = 0; wm < 4; wm++) {
        int ml = wm_base + wm * 16 + gid;
        int r0 = rlist[ml];
        int r1 = rlist[ml + 8];
#pragma unroll
        for (int wn = 0; wn < 4; wn++) {
            int col = n0 + wn_base + wn * 8 + tig * 2;
            float2 bv = *(const float2*)&bias[(size_t)e * ldc + col];
            const float* a = acc[wm][wn];
            if (r0 >= 0) {
                float2 v = make_float2(a[0] + bv.x, a[1] + bv.y);
                if (PHASE == 1) { v.x = fmaxf(v.x, 0.f); v.y = fmaxf(v.y, 0.f); }
                *(float2*)&C[(size_t)r0 * ldc + col] = v;
            }
            if (r1 >= 0) {
                float2 v = make_float2(a[2] + bv.x, a[3] + bv.y);
                if (PHASE == 1) { v.x = fmaxf(v.x, 0.f); v.y = fmaxf(v.y, 0.f); }
                *(float2*)&C[(size_t)r1 * ldc + col] = v;
            }
        }
    }
}

// ---------------- launch ----------------
extern "C" void kernel_launch(void* const* d_in, const int* in_sizes, int n_in,
                              void* d_out, int out_size) {
    const float* x   = (const float*)d_in[0];
    const float* Wr1 = (const float*)d_in[1];
    const float* br1 = (const float*)d_in[2];
    const float* Wr2 = (const float*)d_in[3];
    const float* br2 = (const float*)d_in[4];
    const float* ee  = (const float*)d_in[5];
    const float* We1 = (const float*)d_in[6];
    const float* be1 = (const float*)d_in[7];
    const float* We2 = (const float*)d_in[8];
    const float* be2 = (const float*)d_in[9];
    float* out = (float*)d_out;

    router_kernel<<<N_TOK / 32, 256>>>(x, Wr1, br1, Wr2, br2, ee);
    gumbel_kernel<<<GUM_BLOCKS, 256>>>();
    reduce_kernel<<<1, 32>>>(out, out_size);
    scatter_kernel<<<N_TOK / 256, 256>>>();
    expert_gemm_mma<1><<<dim3(H_DIM / 128, E_EXP * 64), 256>>>(x, We1, be1, nullptr, D_DIM, D_DIM, H_DIM);
    expert_gemm_mma<2><<<dim3(D_DIM / 128, E_EXP * 64), 256>>>(nullptr, We2, be2, out, H_DIM, H_DIM, D_DIM);
}

// round 9
// speedup vs baseline: 3.5066x; 1.1439x over previous
#include <cuda_runtime.h>
#include <cuda_fp16.h>
#include <cstdint>
#include <math.h>

#define N_TOK 8192
#define D_DIM 1024
#define H_DIM 2048
#define E_EXP 8
#define GUM_BLOCKS 32

// ---------------- scratch (no allocs allowed) ----------------
__device__ float g_logits[N_TOK * E_EXP];
__device__ int   g_expert[N_TOK];
__device__ float g_psum[GUM_BLOCKS * E_EXP];
__device__ int   g_pcnt[GUM_BLOCKS * E_EXP];
__device__ float g_pent[GUM_BLOCKS];
__device__ int   g_offsets[E_EXP + 1];
__device__ int   g_cursor[E_EXP];
__device__ int   g_list[N_TOK];
__device__ __half g_hh[(size_t)N_TOK * H_DIM];          // hidden, fp16 (32 MB)
__device__ __half g_xh[(size_t)N_TOK * D_DIM];          // x, fp16 (16 MB)
__device__ __half g_We1h[(size_t)E_EXP * D_DIM * H_DIM]; // We1 fp16 (33.5 MB)
__device__ __half g_We2h[(size_t)E_EXP * H_DIM * D_DIM]; // We2 fp16 (33.5 MB)

// ---------------- threefry2x32 (JAX-compatible, key = (0,42)) ----------------
__device__ __forceinline__ uint32_t rotl32(uint32_t x, uint32_t r) {
    return (x << r) | (x >> (32u - r));
}

__device__ __forceinline__ void threefry2x32_k42(uint32_t c0, uint32_t c1,
                                                 uint32_t& o0, uint32_t& o1) {
    const uint32_t k0 = 0u, k1 = 42u, k2 = 0u ^ 42u ^ 0x1BD11BDAu;
    uint32_t x0 = c0 + k0;
    uint32_t x1 = c1 + k1;
#define TFR(r) { x0 += x1; x1 = rotl32(x1, r); x1 ^= x0; }
    TFR(13u) TFR(15u) TFR(26u) TFR(6u)   x0 += k1; x1 += k2 + 1u;
    TFR(17u) TFR(29u) TFR(16u) TFR(24u)  x0 += k2; x1 += k0 + 2u;
    TFR(13u) TFR(15u) TFR(26u) TFR(6u)   x0 += k0; x1 += k1 + 3u;
    TFR(17u) TFR(29u) TFR(16u) TFR(24u)  x0 += k1; x1 += k2 + 4u;
    TFR(13u) TFR(15u) TFR(26u) TFR(6u)   x0 += k2; x1 += k0 + 5u;
#undef TFR
    o0 = x0; o1 = x1;
}

__device__ __forceinline__ uint32_t jax_random_bits_part(uint32_t idx) {
    uint32_t o0, o1;
    threefry2x32_k42(0u, idx, o0, o1);
    return o0 ^ o1;
}

__device__ __forceinline__ float bits_to_uniform(uint32_t bits) {
    float f = __uint_as_float((bits >> 9) | 0x3f800000u) - 1.0f;
    float v = f * (1.0f - 1e-6f) + 1e-6f;
    return fmaxf(1e-6f, v);
}

// ---------------- fp16 / mma / cp.async helpers ----------------
__device__ __forceinline__ uint32_t f2h2(float a, float b) {
    uint32_t u;
    asm("cvt.rn.f16x2.f32 %0, %1, %2;" : "=r"(u) : "f"(b), "f"(a));
    return u;
}

__device__ __forceinline__ void mma_f16(float* d, const uint32_t* a, const uint32_t* b) {
    asm volatile(
        "mma.sync.aligned.m16n8k16.row.col.f32.f16.f16.f32 "
        "{%0,%1,%2,%3}, {%4,%5,%6,%7}, {%8,%9}, {%0,%1,%2,%3};\n"
        : "+f"(d[0]), "+f"(d[1]), "+f"(d[2]), "+f"(d[3])
        : "r"(a[0]), "r"(a[1]), "r"(a[2]), "r"(a[3]), "r"(b[0]), "r"(b[1]));
}

__device__ __forceinline__ uint32_t smem_u32(const void* p) {
    uint32_t a;
    asm("{ .reg .u64 t; cvta.to.shared.u64 t, %1; cvt.u32.u64 %0, t; }" : "=r"(a) : "l"(p));
    return a;
}

__device__ __forceinline__ void cp_async16(uint32_t dst, const void* src, int src_size) {
    asm volatile("cp.async.cg.shared.global [%0], [%1], 16, %2;"
                 :: "r"(dst), "l"(src), "r"(src_size) : "memory");
}
#define CP_COMMIT() asm volatile("cp.async.commit_group;" ::: "memory")
#define CP_WAIT2()  asm volatile("cp.async.wait_group 2;" ::: "memory")

// ---------------- convert weights + x to fp16 ----------------
#define WE_ELEMS (E_EXP * D_DIM * H_DIM)   // 16777216
#define X_ELEMS  (N_TOK * D_DIM)           // 8388608
__global__ __launch_bounds__(256) void convert_kernel(
    const float* __restrict__ We1, const float* __restrict__ We2,
    const float* __restrict__ x)
{
    int stride = gridDim.x * blockDim.x;
    for (size_t i = blockIdx.x * blockDim.x + threadIdx.x; i < WE_ELEMS / 4; i += stride) {
        float4 v = *(const float4*)(We1 + i * 4);
        uint2 u = make_uint2(f2h2(v.x, v.y), f2h2(v.z, v.w));
        *(uint2*)&g_We1h[i * 4] = u;
        v = *(const float4*)(We2 + i * 4);
        u = make_uint2(f2h2(v.x, v.y), f2h2(v.z, v.w));
        *(uint2*)&g_We2h[i * 4] = u;
    }
    for (size_t i = blockIdx.x * blockDim.x + threadIdx.x; i < X_ELEMS / 4; i += stride) {
        float4 v = *(const float4*)(x + i * 4);
        uint2 u = make_uint2(f2h2(v.x, v.y), f2h2(v.z, v.w));
        *(uint2*)&g_xh[i * 4] = u;
    }
}

// ---------------- router: relu(x@Wr1+b1)@Wr2+b2 @ ee^T -> logits ----------------
__global__ __launch_bounds__(256) void router_kernel(
    const float* __restrict__ x,  const float* __restrict__ Wr1,
    const float* __restrict__ br1, const float* __restrict__ Wr2,
    const float* __restrict__ br2, const float* __restrict__ ee)
{
    __shared__ float xs[32][64];
    __shared__ float ws[64][64];
    __shared__ float t1s[32][64];
    __shared__ float embs[32][64];
    __shared__ float ees[E_EXP][64];

    int tid = threadIdx.x;
    int n0 = blockIdx.x * 32;

    for (int i = tid; i < E_EXP * 64; i += 256)
        ees[i / 64][i % 64] = ee[i];

    int nl = tid >> 3;
    int jb = (tid & 7) << 3;

    float acc[8];
#pragma unroll
    for (int j = 0; j < 8; j++) acc[j] = 0.f;

    for (int k0 = 0; k0 < D_DIM; k0 += 64) {
        {
            int r = tid >> 3, c = (tid & 7) << 3;
            const float* src = x + (size_t)(n0 + r) * D_DIM + k0 + c;
            *(float4*)&xs[r][c]     = *(const float4*)(src);
            *(float4*)&xs[r][c + 4] = *(const float4*)(src + 4);
        }
#pragma unroll
        for (int r = 0; r < 4; r++) {
            int f  = tid + r * 256;
            int kk = f >> 4, j4 = (f & 15) << 2;
            *(float4*)&ws[kk][j4] = *(const float4*)(Wr1 + (size_t)(k0 + kk) * 64 + j4);
        }
        __syncthreads();
#pragma unroll 8
        for (int k = 0; k < 64; k++) {
            float a  = xs[nl][k];
            float4 w0 = *(float4*)&ws[k][jb];
            float4 w1 = *(float4*)&ws[k][jb + 4];
            acc[0] += a * w0.x; acc[1] += a * w0.y; acc[2] += a * w0.z; acc[3] += a * w0.w;
            acc[4] += a * w1.x; acc[5] += a * w1.y; acc[6] += a * w1.z; acc[7] += a * w1.w;
        }
        __syncthreads();
    }
#pragma unroll
    for (int j = 0; j < 8; j++)
        t1s[nl][jb + j] = fmaxf(acc[j] + br1[jb + j], 0.f);

#pragma unroll
    for (int r = 0; r < 4; r++) {
        int f  = tid + r * 256;
        int kk = f >> 4, j4 = (f & 15) << 2;
        *(float4*)&ws[kk][j4] = *(const float4*)(Wr2 + (size_t)kk * 64 + j4);
    }
    __syncthreads();

    float acc2[8];
#pragma unroll
    for (int j = 0; j < 8; j++) acc2[j] = 0.f;
#pragma unroll 8
    for (int k = 0; k < 64; k++) {
        float a  = t1s[nl][k];
        float4 w0 = *(float4*)&ws[k][jb];
        float4 w1 = *(float4*)&ws[k][jb + 4];
        acc2[0] += a * w0.x; acc2[1] += a * w0.y; acc2[2] += a * w0.z; acc2[3] += a * w0.w;
        acc2[4] += a * w1.x; acc2[5] += a * w1.y; acc2[6] += a * w1.z; acc2[7] += a * w1.w;
    }
#pragma unroll
    for (int j = 0; j < 8; j++)
        embs[nl][jb + j] = acc2[j] + br2[jb + j];
    __syncthreads();

    {
        int n = tid >> 3, e = tid & 7;
        float s = 0.f;
#pragma unroll 8
        for (int k = 0; k < 64; k++) s += embs[n][k] * ees[e][k];
        g_logits[(size_t)(n0 + n) * E_EXP + e] = s;
    }
}

// ---------------- gumbel + argmax + softmax stats ----------------
__global__ __launch_bounds__(256) void gumbel_kernel() {
    int tid = threadIdx.x;
    int n = blockIdx.x * 256 + tid;

    float l[E_EXP];
#pragma unroll
    for (int e = 0; e < E_EXP; e++) l[e] = g_logits[(size_t)n * E_EXP + e];

    float mx = l[0];
#pragma unroll
    for (int e = 1; e < E_EXP; e++) mx = fmaxf(mx, l[e]);
    float p[E_EXP], s = 0.f;
#pragma unroll
    for (int e = 0; e < E_EXP; e++) { p[e] = expf(l[e] - mx); s += p[e]; }
    float inv = 1.0f / s;
    float entacc = 0.f;
#pragma unroll
    for (int e = 0; e < E_EXP; e++) {
        p[e] *= inv;
        entacc += p[e] * logf(p[e] + 1e-9f);
    }

    float best = -1e30f; int bi = 0;
#pragma unroll
    for (int e = 0; e < E_EXP; e++) {
        uint32_t bits = jax_random_bits_part((uint32_t)(n * E_EXP + e));
        float u = bits_to_uniform(bits);
        float g = -logf(-logf(u));
        float z = l[e] + g;
        if (z > best) { best = z; bi = e; }
    }
    g_expert[n] = bi;

    __shared__ float sp[E_EXP][256];
    __shared__ int   sc[E_EXP][256];
    __shared__ float se[256];
#pragma unroll
    for (int e = 0; e < E_EXP; e++) { sp[e][tid] = p[e]; sc[e][tid] = (bi == e) ? 1 : 0; }
    se[tid] = entacc;
    __syncthreads();
    for (int st = 128; st > 0; st >>= 1) {
        if (tid < st) {
            se[tid] += se[tid + st];
#pragma unroll
            for (int e = 0; e < E_EXP; e++) {
                sp[e][tid] += sp[e][tid + st];
                sc[e][tid] += sc[e][tid + st];
            }
        }
        __syncthreads();
    }
    if (tid == 0) {
        g_pent[blockIdx.x] = se[0];
#pragma unroll
        for (int e = 0; e < E_EXP; e++) {
            g_psum[blockIdx.x * E_EXP + e] = sp[e][0];
            g_pcnt[blockIdx.x * E_EXP + e] = sc[e][0];
        }
    }
}

// ---------------- final reduce ----------------
__global__ void reduce_kernel(float* __restrict__ out, int out_size) {
    if (threadIdx.x != 0 || blockIdx.x != 0) return;
    float sump[E_EXP]; int cnt[E_EXP]; float ent = 0.f;
    for (int e = 0; e < E_EXP; e++) { sump[e] = 0.f; cnt[e] = 0; }
    for (int b = 0; b < GUM_BLOCKS; b++) {
        ent += g_pent[b];
        for (int e = 0; e < E_EXP; e++) {
            sump[e] += g_psum[b * E_EXP + e];
            cnt[e]  += g_pcnt[b * E_EXP + e];
        }
    }
    float lbl = 0.f;
    for (int e = 0; e < E_EXP; e++)
        lbl += ((float)cnt[e] / (float)N_TOK) * (sump[e] / (float)N_TOK);
    lbl *= (float)E_EXP;
    out[out_size - 2] = lbl;
    out[out_size - 1] = -(ent / (float)N_TOK);

    int off = 0;
    for (int e = 0; e < E_EXP; e++) {
        g_offsets[e] = off;
        off += cnt[e];
        g_cursor[e] = 0;
    }
    g_offsets[E_EXP] = off;
}

// ---------------- scatter ----------------
__global__ __launch_bounds__(256) void scatter_kernel() {
    int n = blockIdx.x * 256 + threadIdx.x;
    int e = g_expert[n];
    int pos = atomicAdd(&g_cursor[e], 1);
    g_list[g_offsets[e] + pos] = n;
}

// ---------------- grouped expert GEMM: fp16 operands, cp.async 4-stage -------
// 128x128 tile, K-step 16. A gathered rows (fp16 gmem), B = fp16 weights.
// A stage: [row][k] halves, row stride 24 halves (48B) -> conflict-free frags
// B stage: [k][n]   halves, k stride 136 halves (272B) -> conflict-free frags
#define A_STR 24
#define B_STR 136
#define NSTAGE 4

template <int PHASE>
__global__ __launch_bounds__(256) void expert_gemm_mma(
    const float* __restrict__ bias, float* __restrict__ Cout,
    int lda, int K, int ldc)
{
    int e  = blockIdx.y >> 6;
    int mt = blockIdx.y & 63;
    int off = g_offsets[e];
    int cnt = g_offsets[e + 1] - off;
    int m0  = mt * 128;
    if (m0 >= cnt) return;

    const __half* A = (PHASE == 2) ? g_hh : g_xh;
    const __half* Wh = ((PHASE == 1) ? g_We1h : g_We2h) + (size_t)e * K * ldc;

    __shared__ __half Abuf[NSTAGE][128 * A_STR];
    __shared__ __half Bbuf[NSTAGE][16 * B_STR];
    __shared__ int rlist[128];

    int tid  = threadIdx.x;
    int wid  = tid >> 5;
    int lane = tid & 31;
    int gid  = lane >> 2;
    int tig  = lane & 3;
    int wm_base = (wid >> 2) * 64;
    int wn_base = (wid & 3) * 32;
    int n0 = blockIdx.x * 128;

    for (int i = tid; i < 128; i += 256) {
        int mi = m0 + i;
        rlist[i] = (mi < cnt) ? g_list[off + mi] : -1;
    }
    __syncthreads();

    // staging roles: 2 cp.async(16B) per thread per stage
    int a_row = tid >> 1, a_ch = tid & 1;          // A: 128 rows x 2 chunks(8 halves)
    int arow_g = rlist[a_row];
    int a_sz = (arow_g >= 0) ? 16 : 0;
    const __half* Asrc = A + (size_t)(arow_g >= 0 ? arow_g : 0) * lda + a_ch * 8;
    uint32_t Adst[NSTAGE];
    int b_k = tid >> 4, b_ch = tid & 15;           // B: 16 k-rows x 16 chunks
    const __half* Bsrc = Wh + (size_t)b_k * ldc + n0 + b_ch * 8;
    uint32_t Bdst[NSTAGE];
#pragma unroll
    for (int s = 0; s < NSTAGE; s++) {
        Adst[s] = smem_u32(&Abuf[s][a_row * A_STR + a_ch * 8]);
        Bdst[s] = smem_u32(&Bbuf[s][b_k * B_STR + b_ch * 8]);
    }

    float acc[4][4][4];
#pragma unroll
    for (int i = 0; i < 4; i++)
#pragma unroll
        for (int j = 0; j < 4; j++)
#pragma unroll
            for (int r = 0; r < 4; r++) acc[i][j][r] = 0.f;

    int T = K / 16;

    // prologue: stages 0..2
#pragma unroll
    for (int s = 0; s < 3; s++) {
        cp_async16(Adst[s], Asrc + s * 16, a_sz);
        cp_async16(Bdst[s], Bsrc + (size_t)s * 16 * ldc, 16);
        CP_COMMIT();
    }

    for (int t = 0; t < T; t++) {
        CP_WAIT2();
        __syncthreads();

        int tn = t + 3;
        if (tn < T) {
            int s = tn & 3;
            cp_async16(Adst[s], Asrc + (size_t)tn * 16, a_sz);
            cp_async16(Bdst[s], Bsrc + (size_t)tn * 16 * ldc, 16);
        }
        CP_COMMIT();

        // compute buf t%4
        {
            const uint32_t* as = (const uint32_t*)Abuf[t & 3];
            const unsigned short* bsh = (const unsigned short*)Bbuf[t & 3];

            uint32_t af[4][4];
#pragma unroll
            for (int wm = 0; wm < 4; wm++) {
                int m = wm_base + wm * 16 + gid;
                af[wm][0] = as[m * (A_STR / 2) + tig];
                af[wm][1] = as[(m + 8) * (A_STR / 2) + tig];
                af[wm][2] = as[m * (A_STR / 2) + tig + 4];
                af[wm][3] = as[(m + 8) * (A_STR / 2) + tig + 4];
            }
            uint32_t bf[4][2];
#pragma unroll
            for (int wn = 0; wn < 4; wn++) {
                int col = wn_base + wn * 8 + gid;
                int k0b = tig * 2;
                uint32_t lo0 = bsh[(k0b)     * B_STR + col];
                uint32_t hi0 = bsh[(k0b + 1) * B_STR + col];
                uint32_t lo1 = bsh[(k0b + 8) * B_STR + col];
                uint32_t hi1 = bsh[(k0b + 9) * B_STR + col];
                bf[wn][0] = lo0 | (hi0 << 16);
                bf[wn][1] = lo1 | (hi1 << 16);
            }
#pragma unroll
            for (int wm = 0; wm < 4; wm++)
#pragma unroll
                for (int wn = 0; wn < 4; wn++)
                    mma_f16(acc[wm][wn], af[wm], bf[wn]);
        }
    }

    // epilogue: bias (+relu); phase1 -> fp16 g_hh, phase2 -> fp32 out
#pragma unroll
    for (int wm = 0; wm < 4; wm++) {
        int ml = wm_base + wm * 16 + gid;
        int r0 = rlist[ml];
        int r1 = rlist[ml + 8];
#pragma unroll
        for (int wn = 0; wn < 4; wn++) {
            int col = n0 + wn_base + wn * 8 + tig * 2;
            float2 bv = *(const float2*)&bias[(size_t)e * ldc + col];
            const float* a = acc[wm][wn];
            if (PHASE == 1) {
                if (r0 >= 0) {
                    float vx = fmaxf(a[0] + bv.x, 0.f), vy = fmaxf(a[1] + bv.y, 0.f);
                    *(uint32_t*)&g_hh[(size_t)r0 * ldc + col] = f2h2(vx, vy);
                }
                if (r1 >= 0) {
                    float vx = fmaxf(a[2] + bv.x, 0.f), vy = fmaxf(a[3] + bv.y, 0.f);
                    *(uint32_t*)&g_hh[(size_t)r1 * ldc + col] = f2h2(vx, vy);
                }
            } else {
                if (r0 >= 0)
                    *(float2*)&Cout[(size_t)r0 * ldc + col] =
                        make_float2(a[0] + bv.x, a[1] + bv.y);
                if (r1 >= 0)
                    *(float2*)&Cout[(size_t)r1 * ldc + col] =
                        make_float2(a[2] + bv.x, a[3] + bv.y);
            }
        }
    }
}

// ---------------- launch ----------------
extern "C" void kernel_launch(void* const* d_in, const int* in_sizes, int n_in,
                              void* d_out, int out_size) {
    const float* x   = (const float*)d_in[0];
    const float* Wr1 = (const float*)d_in[1];
    const float* br1 = (const float*)d_in[2];
    const float* Wr2 = (const float*)d_in[3];
    const float* br2 = (const float*)d_in[4];
    const float* ee  = (const float*)d_in[5];
    const float* We1 = (const float*)d_in[6];
    const float* be1 = (const float*)d_in[7];
    const float* We2 = (const float*)d_in[8];
    const float* be2 = (const float*)d_in[9];
    float* out = (float*)d_out;

    convert_kernel<<<2048, 256>>>(We1, We2, x);
    router_kernel<<<N_TOK / 32, 256>>>(x, Wr1, br1, Wr2, br2, ee);
    gumbel_kernel<<<GUM_BLOCKS, 256>>>();
    reduce_kernel<<<1, 32>>>(out, out_size);
    scatter_kernel<<<N_TOK / 256, 256>>>();
    expert_gemm_mma<1><<<dim3(H_DIM / 128, E_EXP * 64), 256>>>(be1, nullptr, D_DIM, D_DIM, H_DIM);
    expert_gemm_mma<2><<<dim3(D_DIM / 128, E_EXP * 64), 256>>>(be2, out, H_DIM, H_DIM, D_DIM);
}